// round 4
// baseline (speedup 1.0000x reference)
#include <cuda_runtime.h>

namespace {

constexpr int NQ     = 12;
constexpr int DEPTH  = 6;
constexpr int NSTATE = 1 << NQ;        // 4096
constexpr int NT     = 512;            // threads per CTA
constexpr int PT     = NSTATE / NT;    // 8 amplitudes per thread

// Swizzle: phys = i ^ (bit6 -> bit3). Conflict-free for patterns P0/P1/P2
// (varying-bit sets {3:0},{3:0},{0,1,2,6}) and the Gray-composed gather.
__device__ __forceinline__ int sw(int i) { return i ^ ((i >> 3) & 8); }

__device__ __forceinline__ float2 cmul(float2 a, float2 b) {
    float2 r;
    r.x = fmaf(a.x, b.x, -(a.y * b.y));
    r.y = fmaf(a.x, b.y, a.y * b.x);
    return r;
}
__device__ __forceinline__ float2 cmulc(float2 a, float2 b) {  // a * conj(b)
    float2 r;
    r.x = fmaf(a.x, b.x,  a.y * b.y);
    r.y = fmaf(a.y, b.x, -(a.x * b.y));
    return r;
}
// real RY rotation on a pair: na = c*a - s*b ; nb = s*a + c*b
__device__ __forceinline__ void ry_pair(float2& a, float2& b, float c, float s) {
    float2 na, nb;
    na.x = fmaf(c, a.x, -(s * b.x));
    na.y = fmaf(c, a.y, -(s * b.y));
    nb.x = fmaf(s, a.x,   c * b.x);
    nb.y = fmaf(s, a.y,   c * b.y);
    a = na; b = nb;
}

__global__ void __launch_bounds__(NT, 2) qsim_kernel(const float* __restrict__ x,
                                                     const float* __restrict__ params,
                                                     float* __restrict__ out)
{
    __shared__ float2 sS[NSTATE];            // 32 KB state, swizzled
    __shared__ float2 sU0[NQ][4];            // layer-0 full matrices
    __shared__ float  sC [DEPTH][NQ];        // RY cos (d>=1)
    __shared__ float  sSn[DEPTH][NQ];        // RY sin
    __shared__ float2 sB1[DEPTH][NQ];        // B-diag b1 (b0==1 gauge)
    __shared__ float2 sA0[DEPTH][NQ];        // A-diag a0 (temp)
    __shared__ float2 sG [DEPTH][NQ];        // g = a1*conj(a0)
    __shared__ float2 sG0[DEPTH];            // prod_i a0[d][i]
    __shared__ float2 sPhiA[DEPTH - 1][32];      // phase over t bits [8:4]
    __shared__ float2 sPhiB[DEPTH - 1][2][16];   // phase over t bits [3:0] (x t4)
    __shared__ float2 sThi [DEPTH - 1][2][8];    // phase over r bits (x t8)
    __shared__ float  sRed[NT / 32][NQ];

    const int t = threadIdx.x;               // 9 bits
    const int b = blockIdx.x;

    // ========== Stage A: build gates, decompose U = A * RY * B ==========
    if (t < DEPTH * NQ) {
        const int d = t / NQ, i = t % NQ;
        const float* pp = params + (d * NQ + i) * 3;
        float sa, ca, sb, cb, sg, cg;
        sincosf(0.5f * pp[0], &sa, &ca);
        sincosf(0.5f * pp[1], &sb, &cb);
        sincosf(0.5f * pp[2], &sg, &cg);
        float2 m00 = {  cb * ca, -sb * ca };
        float2 m01 = { -cb * sa,  sb * sa };
        float2 m10 = {  cb * sa,  sb * sa };
        float2 m11 = {  cb * ca,  sb * ca };
        float2 u00 = { cg * m00.x + sg * m10.y, cg * m00.y - sg * m10.x };
        float2 u01 = { cg * m01.x + sg * m11.y, cg * m01.y - sg * m11.x };
        float2 u10 = { sg * m00.y + cg * m10.x, -sg * m00.x + cg * m10.y };
        float2 u11 = { sg * m01.y + cg * m11.x, -sg * m01.x + cg * m11.y };
        if (d == 0) {
            float sx, cx;
            sincosf(0.5f * x[b * NQ + i], &sx, &cx);
            float2 v00 = { cx * u00.x + sx * u01.y,  cx * u00.y - sx * u01.x };
            float2 v01 = { sx * u00.y + cx * u01.x, -sx * u00.x + cx * u01.y };
            float2 v10 = { cx * u10.x + sx * u11.y,  cx * u10.y - sx * u11.x };
            float2 v11 = { sx * u10.y + cx * u11.x, -sx * u10.x + cx * u11.y };
            sU0[i][0] = v00; sU0[i][1] = v01; sU0[i][2] = v10; sU0[i][3] = v11;
        } else {
            float c = sqrtf(fmaf(u00.x, u00.x, u00.y * u00.y));
            float s = sqrtf(fmaf(u10.x, u10.x, u10.y * u10.y));
            float2 a0, a1, b1;
            if (s < 1e-12f) {
                float ic = 1.0f / c;
                a0 = { u00.x * ic, u00.y * ic };
                a1 = { u11.x * ic, u11.y * ic };
                b1 = { 1.f, 0.f };
            } else if (c < 1e-12f) {
                float is = 1.0f / s;
                a0 = { -u01.x * is, -u01.y * is };
                a1 = {  u10.x * is,  u10.y * is };
                b1 = { 1.f, 0.f };
            } else {
                float ic = 1.0f / c, is = 1.0f / s;
                a0 = { u00.x * ic, u00.y * ic };
                a1 = { u10.x * is, u10.y * is };
                float2 tb = cmulc(u11, a1);
                b1 = { tb.x * ic, tb.y * ic };
            }
            sC[d][i] = c;  sSn[d][i] = s;
            sB1[d][i] = b1;
            sA0[d][i] = a0;
            sG[d][i]  = cmulc(a1, a0);
        }
    }
    __syncthreads();

    // ========== Stage B: G0[d] = prod_i a0[d][i], d = 1..4 ==========
    if (t >= 1 && t <= 4) {
        float2 p = { 1.f, 0.f };
        #pragma unroll
        for (int i = 0; i < NQ; ++i) p = cmul(p, sA0[t][i]);
        sG0[t] = p;
    }
    __syncthreads();

    // ========== Stage C: factorized diagonal tables ==========
    // dst = (r<<9)|t ; r = wires 0..2 (bits 11..9), t = wires 3..11 (bits 8..0).
    // D_d(dst) = PhiA[t>>4] * PhiB[t4][t&15] * Thi[t8][r]
    if (t < (DEPTH - 1) * 32) {              // PhiA: wires 3..7 B + couplings 4..7 + G0
        const int k = t >> 5, h = t & 31;    // h bits: t8..t4 -> h4..h0
        const int d = k + 1;
        float2 P = (d >= 2) ? sG0[d - 1] : make_float2(1.f, 0.f);
        #pragma unroll
        for (int i = 3; i <= 7; ++i)         // wire i B-phase from bit (11-i) = h bit (i-3 from top): t bit (11-i) = h bit (11-i-4)
            if ((h >> (7 - i)) & 1) P = cmul(P, sB1[d][i]);
        if (d >= 2) {
            if (((h >> 3) ^ (h >> 4)) & 1) P = cmul(P, sG[d - 1][4]);  // bits 7^8
            if (((h >> 2) ^ (h >> 3)) & 1) P = cmul(P, sG[d - 1][5]);  // bits 6^7
            if (((h >> 1) ^ (h >> 2)) & 1) P = cmul(P, sG[d - 1][6]);  // bits 5^6
            if (((h >> 0) ^ (h >> 1)) & 1) P = cmul(P, sG[d - 1][7]);  // bits 4^5
        }
        sPhiA[k][h] = P;
    } else if (t < (DEPTH - 1) * 32 + (DEPTH - 1) * 32) {   // PhiB: wires 8..11 + couplings 8..11
        const int tt = t - (DEPTH - 1) * 32;
        const int k = tt >> 5, e4 = (tt >> 4) & 1, l = tt & 15;   // l = t bits [3:0]
        const int d = k + 1;
        float2 P = { 1.f, 0.f };
        #pragma unroll
        for (int i = 8; i <= 11; ++i)        // wire i from bit (11-i) = l bit (11-i)
            if ((l >> (11 - i)) & 1) P = cmul(P, sB1[d][i]);
        if (d >= 2) {
            if (((l >> 3) ^ e4) & 1)       P = cmul(P, sG[d - 1][8]);   // bits 3^4
            if (((l >> 2) ^ (l >> 3)) & 1) P = cmul(P, sG[d - 1][9]);   // bits 2^3
            if (((l >> 1) ^ (l >> 2)) & 1) P = cmul(P, sG[d - 1][10]);  // bits 1^2
            if (((l >> 0) ^ (l >> 1)) & 1) P = cmul(P, sG[d - 1][11]);  // bits 0^1
        }
        sPhiB[k][e4][l] = P;
    } else if (t < (DEPTH - 1) * 64 + (DEPTH - 1) * 16) {   // Thi: wires 0..3
        const int tt = t - (DEPTH - 1) * 64;
        const int k = tt >> 4, e8 = (tt >> 3) & 1, r = tt & 7;
        const int d = k + 1;
        float2 T = { 1.f, 0.f };
        if ((r >> 2) & 1) T = cmul(T, sB1[d][0]);
        if ((r >> 1) & 1) T = cmul(T, sB1[d][1]);
        if ( r       & 1) T = cmul(T, sB1[d][2]);
        if (d >= 2) {
            int r0 = r & 1, r1 = (r >> 1) & 1, r2 = (r >> 2) & 1;
            if (r2)       T = cmul(T, sG[d - 1][0]);   // bit 11
            if (r1 ^ r2)  T = cmul(T, sG[d - 1][1]);   // bits 10^11
            if (r0 ^ r1)  T = cmul(T, sG[d - 1][2]);   // bits 9^10
            if (e8 ^ r0)  T = cmul(T, sG[d - 1][3]);   // bits 8^9
        }
        sThi[k][e8][r] = T;
    }
    __syncthreads();

    // ========== Layer 0 on |0..0>: product state, written in P0 pattern ==========
    {
        float2 base = { 1.f, 0.f };
        #pragma unroll
        for (int i = 3; i < NQ; ++i) {
            int bit = (t >> (11 - i)) & 1;
            base = cmul(base, sU0[i][bit ? 2 : 0]);
        }
        float2 c01[4];
        #pragma unroll
        for (int h = 0; h < 4; ++h)
            c01[h] = cmul(sU0[0][(h >> 1) ? 2 : 0], sU0[1][(h & 1) ? 2 : 0]);
        #pragma unroll
        for (int r = 0; r < PT; ++r) {
            float2 amp = cmul(cmul(c01[r >> 1], sU0[2][(r & 1) ? 2 : 0]), base);
            sS[sw((r << 9) | t)] = amp;
        }
    }
    __syncthreads();

    // ========== Layers 1..5 ==========
    for (int d = 1; d < DEPTH; ++d) {
        const int k = d - 1;
        float2 s[PT];

        // ---- P0: Gray gather (prev CNOT chain) + diagonal + wires 0..2 ----
        #pragma unroll
        for (int r = 0; r < PT; ++r) {
            int dst = (r << 9) | t;
            int src = dst ^ (dst >> 1);
            s[r] = sS[sw(src)];
        }
        __syncthreads();
        {
            float2 phi = cmul(sPhiA[k][t >> 4], sPhiB[k][(t >> 4) & 1][t & 15]);
            const float2* thi = sThi[k][(t >> 8) & 1];
            #pragma unroll
            for (int r = 0; r < PT; ++r) {
                float2 w = cmul(phi, thi[r]);
                s[r] = cmul(s[r], w);
            }
        }
        #pragma unroll
        for (int j = 0; j < 3; ++j) {        // wire j -> bit 11-j -> local bit 2-j
            const int p = 2 - j;
            const float c = sC[d][j], sn = sSn[d][j];
            #pragma unroll
            for (int m = 0; m < 4; ++m) {
                int lo = m & ((1 << p) - 1);
                int i0 = ((m >> p) << (p + 1)) | lo;
                ry_pair(s[i0], s[i0 | (1 << p)], c, sn);
            }
        }
        #pragma unroll
        for (int r = 0; r < PT; ++r) sS[sw((r << 9) | t)] = s[r];
        __syncthreads();

        // ---- P1: wires 3..5 (idx bits 8..6), per-thread disjoint ----
        const int base1 = ((t >> 6) << 9) | (t & 63);
        #pragma unroll
        for (int r = 0; r < PT; ++r) s[r] = sS[sw(base1 | (r << 6))];
        #pragma unroll
        for (int j = 0; j < 3; ++j) {        // wire 3+j -> bit 8-j -> local bit 2-j
            const int p = 2 - j;
            const float c = sC[d][3 + j], sn = sSn[d][3 + j];
            #pragma unroll
            for (int m = 0; m < 4; ++m) {
                int lo = m & ((1 << p) - 1);
                int i0 = ((m >> p) << (p + 1)) | lo;
                ry_pair(s[i0], s[i0 | (1 << p)], c, sn);
            }
        }
        #pragma unroll
        for (int r = 0; r < PT; ++r) sS[sw(base1 | (r << 6))] = s[r];
        __syncthreads();

        // ---- P2: wires 6..8 (idx bits 5..3, regs) + wires 9..11 (lane bits, shfl) ----
        const int base2 = ((t >> 3) << 6) | (t & 7);
        #pragma unroll
        for (int r = 0; r < PT; ++r) s[r] = sS[sw(base2 | (r << 3))];
        #pragma unroll
        for (int j = 0; j < 3; ++j) {        // wire 6+j -> bit 5-j -> local bit 2-j
            const int p = 2 - j;
            const float c = sC[d][6 + j], sn = sSn[d][6 + j];
            #pragma unroll
            for (int m = 0; m < 4; ++m) {
                int lo = m & ((1 << p) - 1);
                int i0 = ((m >> p) << (p + 1)) | lo;
                ry_pair(s[i0], s[i0 | (1 << p)], c, sn);
            }
        }
        #pragma unroll
        for (int j = 0; j < 3; ++j) {        // wire 9+j -> idx bit 2-j = lane bit 2-j
            const int msk = 1 << (2 - j);
            const float c = sC[d][9 + j], sn = sSn[d][9 + j];
            const float sp = ((t >> (2 - j)) & 1) ? sn : -sn;
            #pragma unroll
            for (int r = 0; r < PT; ++r) {
                float px = __shfl_xor_sync(0xffffffffu, s[r].x, msk);
                float py = __shfl_xor_sync(0xffffffffu, s[r].y, msk);
                s[r].x = fmaf(c, s[r].x, sp * px);
                s[r].y = fmaf(c, s[r].y, sp * py);
            }
        }
        #pragma unroll
        for (int r = 0; r < PT; ++r) sS[sw(base2 | (r << 3))] = s[r];
        __syncthreads();
    }

    // ==== Final: layer-5 CNOT chain folded into the reduction read (P0 gather) ====
    float accLo[3] = { 0.f, 0.f, 0.f };
    float sumAll = 0.f;
    #pragma unroll
    for (int r = 0; r < PT; ++r) {
        int dst = (r << 9) | t;
        int src = dst ^ (dst >> 1);
        float2 a = sS[sw(src)];
        float pr = fmaf(a.x, a.x, a.y * a.y);
        sumAll += pr;
        #pragma unroll
        for (int q = 0; q < 3; ++q)
            accLo[q] += ((r >> (2 - q)) & 1) ? -pr : pr;
    }

    float acc[NQ];
    #pragma unroll
    for (int q = 0; q < 3; ++q) acc[q] = accLo[q];
    #pragma unroll
    for (int q = 3; q < NQ; ++q)
        acc[q] = ((t >> (11 - q)) & 1) ? -sumAll : sumAll;

    #pragma unroll
    for (int q = 0; q < NQ; ++q) {
        #pragma unroll
        for (int off = 16; off; off >>= 1)
            acc[q] += __shfl_xor_sync(0xffffffffu, acc[q], off);
    }
    if ((t & 31) == 0) {
        #pragma unroll
        for (int q = 0; q < NQ; ++q) sRed[t >> 5][q] = acc[q];
    }
    __syncthreads();
    if (t < NQ) {
        float sres = 0.f;
        #pragma unroll
        for (int w = 0; w < NT / 32; ++w) sres += sRed[w][t];
        out[b * NQ + t] = sres;
    }
}

} // namespace

extern "C" void kernel_launch(void* const* d_in, const int* in_sizes, int n_in,
                              void* d_out, int out_size)
{
    (void)n_in; (void)out_size;
    const float* x;
    const float* params;
    if (in_sizes[0] == DEPTH * NQ * 3) {
        params = (const float*)d_in[0];
        x      = (const float*)d_in[1];
    } else {
        x      = (const float*)d_in[0];
        params = (const float*)d_in[1];
    }
    qsim_kernel<<<4096, NT>>>(x, params, (float*)d_out);
}

// round 5
// speedup vs baseline: 1.1334x; 1.1334x over previous
#include <cuda_runtime.h>

namespace {

constexpr int NQ     = 12;
constexpr int DEPTH  = 6;
constexpr int NSTATE = 1 << NQ;        // 4096
constexpr int NT     = 256;            // threads per CTA
constexpr int PT     = NSTATE / NT;    // 16 amplitudes per thread

// XOR swizzle: conflict-free for all round patterns incl. the Gray gather.
__device__ __forceinline__ int sw(int i) { return i ^ ((i >> 4) & 0xF); }

__device__ __forceinline__ float2 cmul(float2 a, float2 b) {
    float2 r;
    r.x = fmaf(a.x, b.x, -(a.y * b.y));
    r.y = fmaf(a.x, b.y, a.y * b.x);
    return r;
}
__device__ __forceinline__ float2 cmulc(float2 a, float2 b) {  // a * conj(b)
    float2 r;
    r.x = fmaf(a.x, b.x,  a.y * b.y);
    r.y = fmaf(a.y, b.x, -(a.x * b.y));
    return r;
}
// real RY rotation on a pair: na = c*a - s*b ; nb = s*a + c*b   (8 FMA)
__device__ __forceinline__ void ry_pair(float2& a, float2& b, float c, float s) {
    float2 na, nb;
    na.x = fmaf(c, a.x, -(s * b.x));
    na.y = fmaf(c, a.y, -(s * b.y));
    nb.x = fmaf(s, a.x,   c * b.x);
    nb.y = fmaf(s, a.y,   c * b.y);
    a = na; b = nb;
}

__global__ void __launch_bounds__(NT, 3) qsim_kernel(const float* __restrict__ x,
                                                     const float* __restrict__ params,
                                                     float* __restrict__ out)
{
    __shared__ float2 sS[NSTATE];          // state (32 KB), swizzled
    __shared__ float2 sU0[NQ][4];          // layer-0 full matrices (batch-dependent)
    __shared__ float  sC[DEPTH][NQ];       // RY cos per (layer, wire), d>=1
    __shared__ float  sSn[DEPTH][NQ];      // RY sin
    __shared__ float2 sB1[DEPTH][NQ];      // B-diag b1 per gate (b0 == 1 gauge), d>=1
    __shared__ float2 sA0[DEPTH][NQ];      // A-diag a0 (temp, for G0)
    __shared__ float2 sG [DEPTH][NQ];      // g = a1*conj(a0) per gate, used for d=1..4
    __shared__ float2 sG0[DEPTH];          // prod_i a0[d][i], d=1..4
    __shared__ float2 sPhi[DEPTH - 1][NT];      // per-layer per-thread fixed-bit phase
    __shared__ float2 sThi[DEPTH - 1][2][16];   // per-layer r-phase (x b7 coupling)
    __shared__ float  sRed[NT / 32][NQ];

    const int t = threadIdx.x;
    const int b = blockIdx.x;

    // ================= Stage A: build gates, decompose U = A * RY * B =======
    if (t < DEPTH * NQ) {
        const int d = t / NQ, i = t % NQ;
        const float* pp = params + (d * NQ + i) * 3;
        float sa, ca, sb, cb, sg, cg;
        sincosf(0.5f * pp[0], &sa, &ca);
        sincosf(0.5f * pp[1], &sb, &cb);
        sincosf(0.5f * pp[2], &sg, &cg);
        // M1 = RZ(beta) @ RY(alpha)
        float2 m00 = {  cb * ca, -sb * ca };
        float2 m01 = { -cb * sa,  sb * sa };
        float2 m10 = {  cb * sa,  sb * sa };
        float2 m11 = {  cb * ca,  sb * ca };
        // U = RX(gamma) @ M1
        float2 u00 = { cg * m00.x + sg * m10.y, cg * m00.y - sg * m10.x };
        float2 u01 = { cg * m01.x + sg * m11.y, cg * m01.y - sg * m11.x };
        float2 u10 = { sg * m00.y + cg * m10.x, -sg * m00.x + cg * m10.y };
        float2 u11 = { sg * m01.y + cg * m11.x, -sg * m01.x + cg * m11.y };
        if (d == 0) {
            // absorb input-encoding RX(x_i); keep layer 0 as full matrices
            float sx, cx;
            sincosf(0.5f * x[b * NQ + i], &sx, &cx);
            float2 v00 = { cx * u00.x + sx * u01.y,  cx * u00.y - sx * u01.x };
            float2 v01 = { sx * u00.y + cx * u01.x, -sx * u00.x + cx * u01.y };
            float2 v10 = { cx * u10.x + sx * u11.y,  cx * u10.y - sx * u11.x };
            float2 v11 = { sx * u10.y + cx * u11.x, -sx * u10.x + cx * u11.y };
            sU0[i][0] = v00; sU0[i][1] = v01; sU0[i][2] = v10; sU0[i][3] = v11;
        } else {
            // numerical split: U = diag(a0,a1) * RY(c,s) * diag(1,b1)
            float c = sqrtf(fmaf(u00.x, u00.x, u00.y * u00.y));
            float s = sqrtf(fmaf(u10.x, u10.x, u10.y * u10.y));
            float2 a0, a1, b1;
            if (s < 1e-12f) {
                float ic = 1.0f / c;
                a0 = { u00.x * ic, u00.y * ic };
                a1 = { u11.x * ic, u11.y * ic };
                b1 = { 1.f, 0.f };
            } else if (c < 1e-12f) {
                float is = 1.0f / s;
                a0 = { -u01.x * is, -u01.y * is };
                a1 = {  u10.x * is,  u10.y * is };
                b1 = { 1.f, 0.f };
            } else {
                float ic = 1.0f / c, is = 1.0f / s;
                a0 = { u00.x * ic, u00.y * ic };
                a1 = { u10.x * is, u10.y * is };
                float2 tb = cmulc(u11, a1);
                b1 = { tb.x * ic, tb.y * ic };
            }
            sC[d][i] = c;  sSn[d][i] = s;
            sB1[d][i] = b1;
            sA0[d][i] = a0;
            sG[d][i]  = cmulc(a1, a0);    // a1 * conj(a0)
        }
    }
    __syncthreads();

    // ================= Stage B: G0[d] = prod_i a0[d][i], d = 1..4 ===========
    if (t >= 1 && t <= 4) {
        float2 p = { 1.f, 0.f };
        #pragma unroll
        for (int i = 0; i < NQ; ++i) p = cmul(p, sA0[t][i]);
        sG0[t] = p;
    }
    __syncthreads();

    // ================= Stage C: diagonal tables =============================
    // dst = (r<<8)|t.  D_d(dst) = Phi[t] * Thi[b7(t)][r].
    #pragma unroll
    for (int k = 0; k < DEPTH - 1; ++k) {
        const int d = k + 1;
        float2 phi = (d >= 2) ? sG0[d - 1] : make_float2(1.f, 0.f);
        #pragma unroll
        for (int i = 4; i < NQ; ++i)
            if ((t >> (11 - i)) & 1) phi = cmul(phi, sB1[d][i]);
        if (d >= 2) {
            #pragma unroll
            for (int i = 5; i < NQ; ++i)
                if (((t >> (11 - i)) ^ (t >> (12 - i))) & 1)
                    phi = cmul(phi, sG[d - 1][i]);
        }
        sPhi[k][t] = phi;
    }
    if (t < (DEPTH - 1) * 32) {
        const int k = t / 32, e = (t >> 4) & 1, r = t & 15;
        const int d = k + 1;
        float2 T = { 1.f, 0.f };
        #pragma unroll
        for (int i = 0; i < 4; ++i)
            if ((r >> (3 - i)) & 1) T = cmul(T, sB1[d][i]);
        if (d >= 2) {
            int r0 = r & 1, r1 = (r >> 1) & 1, r2 = (r >> 2) & 1, r3 = (r >> 3) & 1;
            if (r3)      T = cmul(T, sG[d - 1][0]);
            if (r2 ^ r3) T = cmul(T, sG[d - 1][1]);
            if (r1 ^ r2) T = cmul(T, sG[d - 1][2]);
            if (r0 ^ r1) T = cmul(T, sG[d - 1][3]);
            if (e  ^ r0) T = cmul(T, sG[d - 1][4]);
        }
        sThi[k][e][r] = T;
    }
    __syncthreads();

    // ================= Layer 0 on |0..0>: product state =====================
    {
        float2 phi = { 1.f, 0.f };
        #pragma unroll
        for (int i = 0; i < 8; ++i) {
            int bit = (t >> (7 - i)) & 1;
            phi = cmul(phi, sU0[i][bit ? 2 : 0]);
        }
        float2 c89[4], cAB[4];
        #pragma unroll
        for (int h = 0; h < 4; ++h) {
            c89[h] = cmul(sU0[8][(h >> 1) ? 2 : 0], sU0[9][(h & 1) ? 2 : 0]);
            cAB[h] = cmul(sU0[10][(h >> 1) ? 2 : 0], sU0[11][(h & 1) ? 2 : 0]);
        }
        #pragma unroll
        for (int r = 0; r < PT; ++r)
            sS[sw((t << 4) | r)] = cmul(phi, cmul(c89[r >> 2], cAB[r & 3]));
    }
    __syncthreads();

    // ================= Layers 1..5 ==========================================
    for (int d = 1; d < DEPTH; ++d) {
        const int k = d - 1;
        float2 s[PT];

        // ---- Round C: Gray gather + diagonal (fused into load) + wires 0..3
        {
            const float2 phi = sPhi[k][t];
            const float2* thi = sThi[k][(t >> 7) & 1];
            #pragma unroll
            for (int r = 0; r < PT; ++r) {
                int dst = (r << 8) | t;
                int src = dst ^ (dst >> 1);
                s[r] = cmul(sS[sw(src)], cmul(phi, thi[r]));
            }
        }
        __syncthreads();               // all reads of old state done
        #pragma unroll
        for (int j = 0; j < 4; ++j) {  // wire j -> idx bit 11-j -> local bit 3-j
            const int p = 3 - j;
            const float c = sC[d][j], sn = sSn[d][j];
            #pragma unroll
            for (int m = 0; m < 8; ++m) {
                int lo = m & ((1 << p) - 1);
                int i0 = ((m >> p) << (p + 1)) | lo;
                ry_pair(s[i0], s[i0 | (1 << p)], c, sn);
            }
        }
        #pragma unroll
        for (int r = 0; r < PT; ++r) sS[sw((r << 8) | t)] = s[r];
        __syncthreads();

        // ---- Round B: wires 4..7 (per-thread disjoint read/write: 1 sync) ----
        const int baseB = ((t >> 4) << 8) | (t & 15);
        #pragma unroll
        for (int r = 0; r < PT; ++r) s[r] = sS[sw(baseB | (r << 4))];
        #pragma unroll
        for (int j = 0; j < 4; ++j) {
            const int p = 3 - j;
            const float c = sC[d][4 + j], sn = sSn[d][4 + j];
            #pragma unroll
            for (int m = 0; m < 8; ++m) {
                int lo = m & ((1 << p) - 1);
                int i0 = ((m >> p) << (p + 1)) | lo;
                ry_pair(s[i0], s[i0 | (1 << p)], c, sn);
            }
        }
        #pragma unroll
        for (int r = 0; r < PT; ++r) sS[sw(baseB | (r << 4))] = s[r];
        __syncthreads();

        // ---- Round A: wires 8..11 ----
        #pragma unroll
        for (int r = 0; r < PT; ++r) s[r] = sS[sw((t << 4) | r)];
        #pragma unroll
        for (int j = 0; j < 4; ++j) {
            const int p = 3 - j;
            const float c = sC[d][8 + j], sn = sSn[d][8 + j];
            #pragma unroll
            for (int m = 0; m < 8; ++m) {
                int lo = m & ((1 << p) - 1);
                int i0 = ((m >> p) << (p + 1)) | lo;
                ry_pair(s[i0], s[i0 | (1 << p)], c, sn);
            }
        }
        #pragma unroll
        for (int r = 0; r < PT; ++r) sS[sw((t << 4) | r)] = s[r];
        __syncthreads();
    }

    // ==== Final: layer-5 CNOT chain folded into the reduction read. ====
    float accLo[4];
    #pragma unroll
    for (int q = 0; q < 4; ++q) accLo[q] = 0.f;
    float sumAll = 0.f;
    #pragma unroll
    for (int r = 0; r < PT; ++r) {
        int dst = (r << 8) | t;
        int src = dst ^ (dst >> 1);
        float2 a = sS[sw(src)];
        float pr = fmaf(a.x, a.x, a.y * a.y);
        sumAll += pr;
        #pragma unroll
        for (int q = 0; q < 4; ++q)
            accLo[q] += ((r >> (3 - q)) & 1) ? -pr : pr;
    }

    float acc[NQ];
    #pragma unroll
    for (int q = 0; q < 4; ++q) acc[q] = accLo[q];
    #pragma unroll
    for (int q = 4; q < NQ; ++q)
        acc[q] = ((t >> (11 - q)) & 1) ? -sumAll : sumAll;

    #pragma unroll
    for (int q = 0; q < NQ; ++q) {
        #pragma unroll
        for (int off = 16; off; off >>= 1)
            acc[q] += __shfl_xor_sync(0xffffffffu, acc[q], off);
    }
    if ((t & 31) == 0) {
        #pragma unroll
        for (int q = 0; q < NQ; ++q) sRed[t >> 5][q] = acc[q];
    }
    __syncthreads();
    if (t < NQ) {
        float sres = 0.f;
        #pragma unroll
        for (int w = 0; w < NT / 32; ++w) sres += sRed[w][t];
        out[b * NQ + t] = sres;
    }
}

} // namespace

extern "C" void kernel_launch(void* const* d_in, const int* in_sizes, int n_in,
                              void* d_out, int out_size)
{
    (void)n_in; (void)out_size;
    const float* x;
    const float* params;
    if (in_sizes[0] == DEPTH * NQ * 3) {
        params = (const float*)d_in[0];
        x      = (const float*)d_in[1];
    } else {
        x      = (const float*)d_in[0];
        params = (const float*)d_in[1];
    }
    qsim_kernel<<<4096, NT>>>(x, params, (float*)d_out);
}

// round 6
// speedup vs baseline: 1.2672x; 1.1180x over previous
#include <cuda_runtime.h>

namespace {

constexpr int NQ     = 12;
constexpr int DEPTH  = 6;
constexpr int NSTATE = 1 << NQ;        // 4096
constexpr int NT     = 256;            // threads per CTA
constexpr int PT     = NSTATE / NT;    // 16 amplitudes per thread

// XOR swizzle on float2 elements: phys = i ^ ((i>>4)&0xF)
__device__ __forceinline__ int sw(int i) { return i ^ ((i >> 4) & 0xF); }

__device__ __forceinline__ float2 cmul(float2 a, float2 b) {
    float2 r;
    r.x = fmaf(a.x, b.x, -(a.y * b.y));
    r.y = fmaf(a.x, b.y, a.y * b.x);
    return r;
}
__device__ __forceinline__ float2 cmulc(float2 a, float2 b) {  // a * conj(b)
    float2 r;
    r.x = fmaf(a.x, b.x,  a.y * b.y);
    r.y = fmaf(a.y, b.x, -(a.x * b.y));
    return r;
}
// real RY rotation on a pair: na = c*a - s*b ; nb = s*a + c*b   (8 FMA)
__device__ __forceinline__ void ry_pair(float2& a, float2& b, float c, float s) {
    float2 na, nb;
    na.x = fmaf(c, a.x, -(s * b.x));
    na.y = fmaf(c, a.y, -(s * b.y));
    nb.x = fmaf(s, a.x,   c * b.x);
    nb.y = fmaf(s, a.y,   c * b.y);
    a = na; b = nb;
}

__global__ void __launch_bounds__(NT, 3) qsim_kernel(const float* __restrict__ x,
                                                     const float* __restrict__ params,
                                                     float* __restrict__ out)
{
    __shared__ float2 sS[NSTATE];          // state (32 KB), swizzled
    __shared__ float2 sU0[NQ][4];          // layer-0 full matrices (batch-dependent)
    __shared__ float  sC[DEPTH][NQ];       // RY cos per (layer, wire), d>=1
    __shared__ float  sSn[DEPTH][NQ];      // RY sin
    __shared__ float2 sB1[DEPTH][NQ];      // B-diag b1 (b0 == 1 gauge), d>=1
    __shared__ float2 sA0[DEPTH][NQ];      // A-diag a0 (temp, for G0)
    __shared__ float2 sG [DEPTH][NQ];      // g = a1*conj(a0)
    __shared__ float2 sG0[DEPTH];          // prod_i a0[d][i], d=1..4
    __shared__ float2 sPhi[DEPTH - 1][NT];      // per-layer per-thread fixed-bit phase
    __shared__ float2 sThi[DEPTH - 1][2][16];   // per-layer r-phase (x bit7 coupling)
    __shared__ float2 sW1[2][16];               // layer-1 fused product/diag table
    __shared__ float  sRed[NT / 32][NQ];

    const int t = threadIdx.x;
    const int b = blockIdx.x;

    // ================= Stage A: build gates, decompose U = A * RY * B =======
    if (t < DEPTH * NQ) {
        const int d = t / NQ, i = t % NQ;
        const float* pp = params + (d * NQ + i) * 3;
        float sa, ca, sb, cb, sg, cg;
        sincosf(0.5f * pp[0], &sa, &ca);
        sincosf(0.5f * pp[1], &sb, &cb);
        sincosf(0.5f * pp[2], &sg, &cg);
        float2 m00 = {  cb * ca, -sb * ca };
        float2 m01 = { -cb * sa,  sb * sa };
        float2 m10 = {  cb * sa,  sb * sa };
        float2 m11 = {  cb * ca,  sb * ca };
        float2 u00 = { cg * m00.x + sg * m10.y, cg * m00.y - sg * m10.x };
        float2 u01 = { cg * m01.x + sg * m11.y, cg * m01.y - sg * m11.x };
        float2 u10 = { sg * m00.y + cg * m10.x, -sg * m00.x + cg * m10.y };
        float2 u11 = { sg * m01.y + cg * m11.x, -sg * m01.x + cg * m11.y };
        if (d == 0) {
            float sx, cx;
            sincosf(0.5f * x[b * NQ + i], &sx, &cx);
            float2 v00 = { cx * u00.x + sx * u01.y,  cx * u00.y - sx * u01.x };
            float2 v01 = { sx * u00.y + cx * u01.x, -sx * u00.x + cx * u01.y };
            float2 v10 = { cx * u10.x + sx * u11.y,  cx * u10.y - sx * u11.x };
            float2 v11 = { sx * u10.y + cx * u11.x, -sx * u10.x + cx * u11.y };
            sU0[i][0] = v00; sU0[i][1] = v01; sU0[i][2] = v10; sU0[i][3] = v11;
        } else {
            float c = sqrtf(fmaf(u00.x, u00.x, u00.y * u00.y));
            float s = sqrtf(fmaf(u10.x, u10.x, u10.y * u10.y));
            float2 a0, a1, b1;
            if (s < 1e-12f) {
                float ic = 1.0f / c;
                a0 = { u00.x * ic, u00.y * ic };
                a1 = { u11.x * ic, u11.y * ic };
                b1 = { 1.f, 0.f };
            } else if (c < 1e-12f) {
                float is = 1.0f / s;
                a0 = { -u01.x * is, -u01.y * is };
                a1 = {  u10.x * is,  u10.y * is };
                b1 = { 1.f, 0.f };
            } else {
                float ic = 1.0f / c, is = 1.0f / s;
                a0 = { u00.x * ic, u00.y * ic };
                a1 = { u10.x * is, u10.y * is };
                float2 tb = cmulc(u11, a1);
                b1 = { tb.x * ic, tb.y * ic };
            }
            sC[d][i] = c;  sSn[d][i] = s;
            sB1[d][i] = b1;
            sA0[d][i] = a0;
            sG[d][i]  = cmulc(a1, a0);
        }
    }
    __syncthreads();

    // ================= Stage B: G0[d] = prod_i a0[d][i], d = 1..4 ===========
    if (t >= 1 && t <= 4) {
        float2 p = { 1.f, 0.f };
        #pragma unroll
        for (int i = 0; i < NQ; ++i) p = cmul(p, sA0[t][i]);
        sG0[t] = p;
    }
    __syncthreads();

    // ================= Stage C: diagonal tables =============================
    // dst = (r<<8)|t.  D_d(dst) = Phi[t] * Thi[bit7(t)][r].
    #pragma unroll
    for (int k = 0; k < DEPTH - 1; ++k) {
        const int d = k + 1;
        float2 phi = (d >= 2) ? sG0[d - 1] : make_float2(1.f, 0.f);
        #pragma unroll
        for (int i = 4; i < NQ; ++i)
            if ((t >> (11 - i)) & 1) phi = cmul(phi, sB1[d][i]);
        if (d >= 2) {
            #pragma unroll
            for (int i = 5; i < NQ; ++i)
                if (((t >> (11 - i)) ^ (t >> (12 - i))) & 1)
                    phi = cmul(phi, sG[d - 1][i]);
        }
        sPhi[k][t] = phi;
    }
    if (t < (DEPTH - 1) * 32) {
        const int k = t / 32, e = (t >> 4) & 1, r = t & 15;
        const int d = k + 1;
        float2 T = { 1.f, 0.f };
        #pragma unroll
        for (int i = 0; i < 4; ++i)
            if ((r >> (3 - i)) & 1) T = cmul(T, sB1[d][i]);
        if (d >= 2) {
            int r0 = r & 1, r1 = (r >> 1) & 1, r2 = (r >> 2) & 1, r3 = (r >> 3) & 1;
            if (r3)      T = cmul(T, sG[d - 1][0]);
            if (r2 ^ r3) T = cmul(T, sG[d - 1][1]);
            if (r1 ^ r2) T = cmul(T, sG[d - 1][2]);
            if (r0 ^ r1) T = cmul(T, sG[d - 1][3]);
            if (e  ^ r0) T = cmul(T, sG[d - 1][4]);
        }
        sThi[k][e][r] = T;
    }
    __syncthreads();

    // ================= Stage D: layer-1 fused table + per-thread phiF =======
    // Layer-1 round C works on the Gray-gathered product state:
    //   src = (gray(r)<<8) | (gt ^ (r0<<7)),  gt = t ^ (t>>1)
    //   amp(src)*D_1(dst) = sW1[t7][r] * phiF(t)
    if (t < 32) {
        const int e = t >> 4, r = t & 15;
        const int gr = r ^ (r >> 1);
        float2 c01 = cmul(sU0[0][(gr & 8) ? 2 : 0], sU0[1][(gr & 4) ? 2 : 0]);
        float2 c23 = cmul(sU0[2][(gr & 2) ? 2 : 0], sU0[3][(gr & 1) ? 2 : 0]);
        float2 u4  = sU0[4][((e ^ r) & 1) ? 2 : 0];
        sW1[e][r] = cmul(cmul(c01, c23), cmul(u4, sThi[0][0][r]));
    }
    const int gt = t ^ (t >> 1);
    float2 phiF = sPhi[0][t];
    #pragma unroll
    for (int i = 5; i < NQ; ++i) {
        int bit = (gt >> (11 - i)) & 1;
        phiF = cmul(phiF, sU0[i][bit ? 2 : 0]);
    }
    __syncthreads();

    // ===== addressing bases (all hot-loop addresses are base ^ const) ======
    const int swt   = sw(t);                       // C store:  (r<<8) | swt
    const int swgt  = sw(gt);                      // C gather: swgt ^ CR(r)
    const int baseB = ((t >> 4) << 8) | (t & 15);  // B:        baseB ^ 17r
    const int swA   = (t << 4) | (t & 15);         // A:        swA ^ r

    float2 s[PT];

    // ================= Layers 1..5 ==========================================
    for (int d = 1; d < DEPTH; ++d) {
        // ---- Round C: wires 0..3 ----
        if (d == 1) {
            const float2* w1 = sW1[t >> 7];
            #pragma unroll
            for (int r = 0; r < PT; ++r) s[r] = cmul(w1[r], phiF);
        } else {
            const int k = d - 1;
            const float2 phi = sPhi[k][t];
            const float2* thi = sThi[k][(t >> 7) & 1];
            #pragma unroll
            for (int r = 0; r < PT; ++r) {
                const int gr = r ^ (r >> 1);
                const int cr = (gr << 8) ^ ((r & 1) << 7) ^ ((r & 1) << 3);
                s[r] = cmul(sS[swgt ^ cr], cmul(phi, thi[r]));
            }
            __syncthreads();           // all reads of old state done
        }
        #pragma unroll
        for (int j = 0; j < 4; ++j) {  // wire j -> local bit 3-j
            const int p = 3 - j;
            const float c = sC[d][j], sn = sSn[d][j];
            #pragma unroll
            for (int m = 0; m < 8; ++m) {
                int lo = m & ((1 << p) - 1);
                int i0 = ((m >> p) << (p + 1)) | lo;
                ry_pair(s[i0], s[i0 | (1 << p)], c, sn);
            }
        }
        #pragma unroll
        for (int r = 0; r < PT; ++r) sS[(r << 8) | swt] = s[r];
        __syncthreads();

        // ---- Round B: wires 4..7 (per-thread disjoint addresses) ----
        #pragma unroll
        for (int r = 0; r < PT; ++r) s[r] = sS[baseB ^ (17 * r)];
        #pragma unroll
        for (int j = 0; j < 4; ++j) {
            const int p = 3 - j;
            const float c = sC[d][4 + j], sn = sSn[d][4 + j];
            #pragma unroll
            for (int m = 0; m < 8; ++m) {
                int lo = m & ((1 << p) - 1);
                int i0 = ((m >> p) << (p + 1)) | lo;
                ry_pair(s[i0], s[i0 | (1 << p)], c, sn);
            }
        }
        #pragma unroll
        for (int r = 0; r < PT; ++r) sS[baseB ^ (17 * r)] = s[r];
        __syncthreads();

        // ---- Round A: wires 8..11 ----
        #pragma unroll
        for (int r = 0; r < PT; ++r) s[r] = sS[swA ^ r];
        #pragma unroll
        for (int j = 0; j < 4; ++j) {
            const int p = 3 - j;
            const float c = sC[d][8 + j], sn = sSn[d][8 + j];
            #pragma unroll
            for (int m = 0; m < 8; ++m) {
                int lo = m & ((1 << p) - 1);
                int i0 = ((m >> p) << (p + 1)) | lo;
                ry_pair(s[i0], s[i0 | (1 << p)], c, sn);
            }
        }
        if (d < DEPTH - 1) {
            #pragma unroll
            for (int r = 0; r < PT; ++r) sS[swA ^ r] = s[r];
            __syncthreads();
        }
    }

    // ==== Final reduction directly from registers (idx = (t<<4)|r). ====
    // Layer-5 CNOT chain = permutation dst = grayinv(idx); signs:
    //   wire q (0..7):  prefix-XOR of t bits 7..(7-q)
    //   wire q (8..11): parity(t) ^ prefix-XOR of r bits
    float accLo[4] = { 0.f, 0.f, 0.f, 0.f };
    float sumAll = 0.f;
    #pragma unroll
    for (int r = 0; r < PT; ++r) {
        float pr = fmaf(s[r].x, s[r].x, s[r].y * s[r].y);
        sumAll += pr;
        const int r3 = (r >> 3) & 1, r2 = (r >> 2) & 1, r1 = (r >> 1) & 1, r0 = r & 1;
        const int p8 = r3, p9 = r3 ^ r2, p10 = p9 ^ r1, p11 = p10 ^ r0;
        accLo[0] += p8  ? -pr : pr;
        accLo[1] += p9  ? -pr : pr;
        accLo[2] += p10 ? -pr : pr;
        accLo[3] += p11 ? -pr : pr;
    }

    float acc[NQ];
    int pref = 0;
    #pragma unroll
    for (int q = 0; q < 8; ++q) {
        pref ^= (t >> (7 - q)) & 1;
        acc[q] = pref ? -sumAll : sumAll;
    }
    const int ptp = pref;                       // parity of t
    #pragma unroll
    for (int q = 0; q < 4; ++q) acc[8 + q] = ptp ? -accLo[q] : accLo[q];

    #pragma unroll
    for (int q = 0; q < NQ; ++q) {
        #pragma unroll
        for (int off = 16; off; off >>= 1)
            acc[q] += __shfl_xor_sync(0xffffffffu, acc[q], off);
    }
    if ((t & 31) == 0) {
        #pragma unroll
        for (int q = 0; q < NQ; ++q) sRed[t >> 5][q] = acc[q];
    }
    __syncthreads();
    if (t < NQ) {
        float sres = 0.f;
        #pragma unroll
        for (int w = 0; w < NT / 32; ++w) sres += sRed[w][t];
        out[b * NQ + t] = sres;
    }
}

} // namespace

extern "C" void kernel_launch(void* const* d_in, const int* in_sizes, int n_in,
                              void* d_out, int out_size)
{
    (void)n_in; (void)out_size;
    const float* x;
    const float* params;
    if (in_sizes[0] == DEPTH * NQ * 3) {
        params = (const float*)d_in[0];
        x      = (const float*)d_in[1];
    } else {
        x      = (const float*)d_in[0];
        params = (const float*)d_in[1];
    }
    qsim_kernel<<<4096, NT>>>(x, params, (float*)d_out);
}

// round 8
// speedup vs baseline: 1.4728x; 1.1622x over previous
#include <cuda_runtime.h>

namespace {

constexpr int NQ     = 12;
constexpr int DEPTH  = 6;
constexpr int NSTATE = 1 << NQ;        // 4096
constexpr int NT     = 256;            // threads per CTA
constexpr int PT     = NSTATE / NT;    // 16 amplitudes per thread

// XOR swizzle on float2 elements: phys = i ^ ((i>>4)&0xF). GF(2)-linear.
__device__ __forceinline__ int sw(int i) { return i ^ ((i >> 4) & 0xF); }

__device__ __forceinline__ float2 cmul(float2 a, float2 b) {
    float2 r;
    r.x = fmaf(a.x, b.x, -(a.y * b.y));
    r.y = fmaf(a.x, b.y, a.y * b.x);
    return r;
}
__device__ __forceinline__ float2 cmulc(float2 a, float2 b) {  // a * conj(b)
    float2 r;
    r.x = fmaf(a.x, b.x,  a.y * b.y);
    r.y = fmaf(a.y, b.x, -(a.x * b.y));
    return r;
}
// shear pair (fast Givens): na = a - t*b ; nb = t*a + b   (4 FMA total)
__device__ __forceinline__ void sh_pair(float2& a, float2& b, float tv) {
    float2 na, nb;
    na.x = fmaf(-tv, b.x, a.x);
    na.y = fmaf(-tv, b.y, a.y);
    nb.x = fmaf( tv, a.x, b.x);
    nb.y = fmaf( tv, a.y, b.y);
    a = na; b = nb;
}

__global__ void __launch_bounds__(NT, 3) qsim_kernel(const float* __restrict__ x,
                                                     const float* __restrict__ params,
                                                     float* __restrict__ out)
{
    __shared__ float2 sS[NSTATE];          // state (32 KB), swizzled
    __shared__ float2 sU0[NQ][4];          // layer-0 full matrices (batch-dependent)
    __shared__ float  sT [DEPTH][NQ];      // shear coeff t = s'/c' (<=1), d>=1
    __shared__ float  sSc[DEPTH][NQ];      // per-gate scale c' (folded into phi)
    __shared__ float2 sB1[DEPTH][NQ];      // B-diag b1 (b0 == 1 gauge), d>=1
    __shared__ float2 sA0[DEPTH][NQ];      // A-diag a0 (temp, for G0)
    __shared__ float2 sG [DEPTH][NQ];      // g = a1*conj(a0)
    __shared__ float2 sG0[DEPTH];          // prod_i a0[d][i], d=1..4
    __shared__ float  sCd[DEPTH];          // prod_i scale[d][i], d=1..5
    __shared__ int    sM [DEPTH];          // per-layer X-flip mask (wire i -> bit 11-i)
    __shared__ float2 sPhi[DEPTH - 1][NT];      // per-layer per-thread fixed-bit phase
    __shared__ float2 sThi[DEPTH - 1][2][16];   // per-layer r-phase (x bit7 coupling)
    __shared__ float2 sW1[2][16];               // layer-1 fused product/diag table
    __shared__ float  sRed[NT / 32][NQ];

    const int t = threadIdx.x;
    const int b = blockIdx.x;

    if (t < DEPTH) sM[t] = 0;
    __syncthreads();

    // ================= Stage A: build gates; decompose U = (A*RY*B)*X =======
    if (t < DEPTH * NQ) {
        const int d = t / NQ, i = t % NQ;
        const float* pp = params + (d * NQ + i) * 3;
        float sa, ca, sb, cb, sg, cg;
        sincosf(0.5f * pp[0], &sa, &ca);
        sincosf(0.5f * pp[1], &sb, &cb);
        sincosf(0.5f * pp[2], &sg, &cg);
        float2 m00 = {  cb * ca, -sb * ca };
        float2 m01 = { -cb * sa,  sb * sa };
        float2 m10 = {  cb * sa,  sb * sa };
        float2 m11 = {  cb * ca,  sb * ca };
        float2 u00 = { cg * m00.x + sg * m10.y, cg * m00.y - sg * m10.x };
        float2 u01 = { cg * m01.x + sg * m11.y, cg * m01.y - sg * m11.x };
        float2 u10 = { sg * m00.y + cg * m10.x, -sg * m00.x + cg * m10.y };
        float2 u11 = { sg * m01.y + cg * m11.x, -sg * m01.x + cg * m11.y };
        if (d == 0) {
            float sx, cx;
            sincosf(0.5f * x[b * NQ + i], &sx, &cx);
            float2 v00 = { cx * u00.x + sx * u01.y,  cx * u00.y - sx * u01.x };
            float2 v01 = { sx * u00.y + cx * u01.x, -sx * u00.x + cx * u01.y };
            float2 v10 = { cx * u10.x + sx * u11.y,  cx * u10.y - sx * u11.x };
            float2 v11 = { sx * u10.y + cx * u11.x, -sx * u10.x + cx * u11.y };
            sU0[i][0] = v00; sU0[i][1] = v01; sU0[i][2] = v10; sU0[i][3] = v11;
        } else {
            float n00 = fmaf(u00.x, u00.x, u00.y * u00.y);   // |u00|^2
            float n10 = fmaf(u10.x, u10.x, u10.y * u10.y);   // |u10|^2
            bool swp = n10 > n00;     // V = U*X (column swap) so c' >= s'
            float2 v00, v10, v11;
            if (swp) { v00 = u01; v10 = u11; v11 = u10; atomicOr(&sM[d], 1 << (11 - i)); }
            else     { v00 = u00; v10 = u10; v11 = u11; }
            float c = sqrtf(fmaf(v00.x, v00.x, v00.y * v00.y));
            float s = sqrtf(fmaf(v10.x, v10.x, v10.y * v10.y));
            float ic = 1.0f / c;
            float2 a0 = { v00.x * ic, v00.y * ic };
            float2 a1, b1;
            if (s < 1e-12f) {
                a1 = { v11.x * ic, v11.y * ic };
                b1 = { 1.f, 0.f };
            } else {
                float is = 1.0f / s;
                a1 = { v10.x * is, v10.y * is };
                float2 tb = cmulc(v11, a1);
                b1 = { tb.x * ic, tb.y * ic };
            }
            sT [d][i] = s * ic;       // t = s/c <= 1
            sSc[d][i] = c;
            sB1[d][i] = b1;
            sA0[d][i] = a0;
            sG [d][i] = cmulc(a1, a0);
        }
    }
    __syncthreads();

    // ================= Stage B: per-layer products =========================
    if (t >= 1 && t <= 5) {
        float cs = 1.f;
        #pragma unroll
        for (int i = 0; i < NQ; ++i) cs *= sSc[t][i];
        sCd[t] = cs;
        if (t <= 4) {
            float2 p = { 1.f, 0.f };
            #pragma unroll
            for (int i = 0; i < NQ; ++i) p = cmul(p, sA0[t][i]);
            sG0[t] = p;
        }
    }
    __syncthreads();

    // ================= Stage C: diagonal tables ============================
    // Layer d: src = gray(dst ^ m_d) = gray(dst) ^ gm_d, gm = m ^ (m>>1).
    // B_d is dst-indexed (post-X); propagated A_{d-1} is src-indexed.
    #pragma unroll
    for (int k = 0; k < DEPTH - 1; ++k) {
        const int d = k + 1;
        const int mm = sM[d];
        const int gm = mm ^ (mm >> 1);
        float2 phi = (d >= 2) ? sG0[d - 1] : make_float2(1.f, 0.f);
        const float cd = sCd[d];
        phi.x *= cd; phi.y *= cd;
        #pragma unroll
        for (int i = 4; i < NQ; ++i)
            if ((t >> (11 - i)) & 1) phi = cmul(phi, sB1[d][i]);
        if (d >= 2) {
            #pragma unroll
            for (int i = 5; i < NQ; ++i)
                if (((t >> (11 - i)) ^ (t >> (12 - i)) ^ (gm >> (11 - i))) & 1)
                    phi = cmul(phi, sG[d - 1][i]);
        }
        sPhi[k][t] = phi;
    }
    if (t < (DEPTH - 1) * 32) {
        const int k = t / 32, e = (t >> 4) & 1, r = t & 15;
        const int d = k + 1;
        const int mm = sM[d];
        const int gm = mm ^ (mm >> 1);
        float2 T = { 1.f, 0.f };
        #pragma unroll
        for (int i = 0; i < 4; ++i)
            if ((r >> (3 - i)) & 1) T = cmul(T, sB1[d][i]);
        if (d >= 2) {
            int r0 = r & 1, r1 = (r >> 1) & 1, r2 = (r >> 2) & 1, r3 = (r >> 3) & 1;
            if ((r3      ^ (gm >> 11)) & 1) T = cmul(T, sG[d - 1][0]);
            if ((r2 ^ r3 ^ (gm >> 10)) & 1) T = cmul(T, sG[d - 1][1]);
            if ((r1 ^ r2 ^ (gm >>  9)) & 1) T = cmul(T, sG[d - 1][2]);
            if ((r0 ^ r1 ^ (gm >>  8)) & 1) T = cmul(T, sG[d - 1][3]);
            if ((e  ^ r0 ^ (gm >>  7)) & 1) T = cmul(T, sG[d - 1][4]);
        }
        sThi[k][e][r] = T;
    }
    __syncthreads();

    // ================= Stage D: layer-1 fused table + per-thread phiF ======
    // Layer-1 reads product state at src = gray(dst) ^ gm1.
    const int m1g = sM[1] ^ (sM[1] >> 1);
    if (t < 32) {
        const int e = t >> 4, r = t & 15;
        const int gr = (r ^ (r >> 1)) ^ ((m1g >> 8) & 15);
        float2 c01 = cmul(sU0[0][(gr & 8) ? 2 : 0], sU0[1][(gr & 4) ? 2 : 0]);
        float2 c23 = cmul(sU0[2][(gr & 2) ? 2 : 0], sU0[3][(gr & 1) ? 2 : 0]);
        float2 u4  = sU0[4][((e ^ r ^ (m1g >> 7)) & 1) ? 2 : 0];
        sW1[e][r] = cmul(cmul(c01, c23), cmul(u4, sThi[0][0][r]));
    }
    const int gt = t ^ (t >> 1);
    float2 phiF = sPhi[0][t];
    {
        const int gmix = gt ^ m1g;
        #pragma unroll
        for (int i = 5; i < NQ; ++i) {
            int bit = (gmix >> (11 - i)) & 1;
            phiF = cmul(phiF, sU0[i][bit ? 2 : 0]);
        }
    }
    __syncthreads();

    // ===== addressing bases (hot-loop addresses are base ^ const) ==========
    const int swt   = sw(t);                       // C store:  (r<<8) | swt
    const int swgt  = sw(gt);                      // C gather: (swgt^sw(gm)) ^ CR(r)
    const int baseB = ((t >> 4) << 8) | (t & 15);  // B:        baseB ^ 17r
    const int swA   = (t << 4) | (t & 15);         // A:        swA ^ r

    float2 s[PT];

    // ================= Layers 1..5 =========================================
    for (int d = 1; d < DEPTH; ++d) {
        // ---- Round C: wires 0..3 ----
        if (d == 1) {
            const float2* w1 = sW1[t >> 7];
            #pragma unroll
            for (int r = 0; r < PT; ++r) s[r] = cmul(w1[r], phiF);
        } else {
            const int k = d - 1;
            const int mm = sM[d];
            const int gm = mm ^ (mm >> 1);
            const int gbase = swgt ^ sw(gm);       // sw, gray are GF(2)-linear
            const float2 phi = sPhi[k][t];
            const float2* thi = sThi[k][(t >> 7) & 1];
            #pragma unroll
            for (int r = 0; r < PT; ++r) {
                const int gr = r ^ (r >> 1);
                const int cr = (gr << 8) ^ ((r & 1) << 7) ^ ((r & 1) << 3);
                s[r] = cmul(sS[gbase ^ cr], cmul(phi, thi[r]));
            }
            __syncthreads();           // all reads of old state done
        }
        #pragma unroll
        for (int j = 0; j < 4; ++j) {  // wire j -> local bit 3-j
            const int p = 3 - j;
            const float tv = sT[d][j];
            #pragma unroll
            for (int m = 0; m < 8; ++m) {
                int lo = m & ((1 << p) - 1);
                int i0 = ((m >> p) << (p + 1)) | lo;
                sh_pair(s[i0], s[i0 | (1 << p)], tv);
            }
        }
        #pragma unroll
        for (int r = 0; r < PT; ++r) sS[(r << 8) | swt] = s[r];
        __syncthreads();

        // ---- Round B: wires 4..7 (per-thread disjoint addresses) ----
        #pragma unroll
        for (int r = 0; r < PT; ++r) s[r] = sS[baseB ^ (17 * r)];
        #pragma unroll
        for (int j = 0; j < 4; ++j) {
            const int p = 3 - j;
            const float tv = sT[d][4 + j];
            #pragma unroll
            for (int m = 0; m < 8; ++m) {
                int lo = m & ((1 << p) - 1);
                int i0 = ((m >> p) << (p + 1)) | lo;
                sh_pair(s[i0], s[i0 | (1 << p)], tv);
            }
        }
        #pragma unroll
        for (int r = 0; r < PT; ++r) sS[baseB ^ (17 * r)] = s[r];
        __syncthreads();

        // ---- Round A: wires 8..11 ----
        #pragma unroll
        for (int r = 0; r < PT; ++r) s[r] = sS[swA ^ r];
        #pragma unroll
        for (int j = 0; j < 4; ++j) {
            const int p = 3 - j;
            const float tv = sT[d][8 + j];
            #pragma unroll
            for (int m = 0; m < 8; ++m) {
                int lo = m & ((1 << p) - 1);
                int i0 = ((m >> p) << (p + 1)) | lo;
                sh_pair(s[i0], s[i0 | (1 << p)], tv);
            }
        }
        if (d < DEPTH - 1) {
            #pragma unroll
            for (int r = 0; r < PT; ++r) sS[swA ^ r] = s[r];
            __syncthreads();
        }
    }

    // ==== Final reduction directly from registers (idx = (t<<4)|r). ====
    float accLo[4] = { 0.f, 0.f, 0.f, 0.f };
    float sumAll = 0.f;
    #pragma unroll
    for (int r = 0; r < PT; ++r) {
        float pr = fmaf(s[r].x, s[r].x, s[r].y * s[r].y);
        sumAll += pr;
        const int r3 = (r >> 3) & 1, r2 = (r >> 2) & 1, r1 = (r >> 1) & 1, r0 = r & 1;
        const int p8 = r3, p9 = r3 ^ r2, p10 = p9 ^ r1, p11 = p10 ^ r0;
        accLo[0] += p8  ? -pr : pr;
        accLo[1] += p9  ? -pr : pr;
        accLo[2] += p10 ? -pr : pr;
        accLo[3] += p11 ? -pr : pr;
    }

    float acc[NQ];
    int pref = 0;
    #pragma unroll
    for (int q = 0; q < 8; ++q) {
        pref ^= (t >> (7 - q)) & 1;
        acc[q] = pref ? -sumAll : sumAll;
    }
    const int ptp = pref;
    #pragma unroll
    for (int q = 0; q < 4; ++q) acc[8 + q] = ptp ? -accLo[q] : accLo[q];

    #pragma unroll
    for (int q = 0; q < NQ; ++q) {
        #pragma unroll
        for (int off = 16; off; off >>= 1)
            acc[q] += __shfl_xor_sync(0xffffffffu, acc[q], off);
    }
    if ((t & 31) == 0) {
        #pragma unroll
        for (int q = 0; q < NQ; ++q) sRed[t >> 5][q] = acc[q];
    }
    __syncthreads();
    if (t < NQ) {
        float sres = 0.f;
        #pragma unroll
        for (int w = 0; w < NT / 32; ++w) sres += sRed[w][t];
        out[b * NQ + t] = sres;
    }
}

} // namespace

extern "C" void kernel_launch(void* const* d_in, const int* in_sizes, int n_in,
                              void* d_out, int out_size)
{
    (void)n_in; (void)out_size;
    const float* x;
    const float* params;
    if (in_sizes[0] == DEPTH * NQ * 3) {
        params = (const float*)d_in[0];
        x      = (const float*)d_in[1];
    } else {
        x      = (const float*)d_in[0];
        params = (const float*)d_in[1];
    }
    qsim_kernel<<<4096, NT>>>(x, params, (float*)d_out);
}

// round 9
// speedup vs baseline: 1.4781x; 1.0036x over previous
#include <cuda_runtime.h>

namespace {

constexpr int NQ     = 12;
constexpr int DEPTH  = 6;
constexpr int NSTATE = 1 << NQ;        // 4096
constexpr int NT     = 256;            // threads per CTA
constexpr int PT     = NSTATE / NT;    // 16 amplitudes per thread

// XOR swizzle on float2 elements: phys = i ^ ((i>>4)&0xF). GF(2)-linear.
__device__ __forceinline__ int sw(int i) { return i ^ ((i >> 4) & 0xF); }

__device__ __forceinline__ float2 cmul(float2 a, float2 b) {
    float2 r;
    r.x = fmaf(a.x, b.x, -(a.y * b.y));
    r.y = fmaf(a.x, b.y, a.y * b.x);
    return r;
}
__device__ __forceinline__ float2 cmulc(float2 a, float2 b) {  // a * conj(b)
    float2 r;
    r.x = fmaf(a.x, b.x,  a.y * b.y);
    r.y = fmaf(a.y, b.x, -(a.x * b.y));
    return r;
}
// shear pair (fast Givens): na = a - t*b ; nb = t*a + b   (4 FMA total)
__device__ __forceinline__ void sh_pair(float2& a, float2& b, float tv) {
    float2 na, nb;
    na.x = fmaf(-tv, b.x, a.x);
    na.y = fmaf(-tv, b.y, a.y);
    nb.x = fmaf( tv, a.x, b.x);
    nb.y = fmaf( tv, a.y, b.y);
    a = na; b = nb;
}

__global__ void __launch_bounds__(NT, 4) qsim_kernel(const float* __restrict__ x,
                                                     const float* __restrict__ params,
                                                     float* __restrict__ out)
{
    __shared__ float2 sS[NSTATE];          // state (32 KB), swizzled
    __shared__ float2 sU0[NQ][4];          // layer-0 full matrices (batch-dependent)
    __shared__ float  sT [DEPTH][NQ];      // shear coeff t = s'/c' (<=1), d>=1
    __shared__ float  sSc[DEPTH][NQ];      // per-gate scale c' (folded into phi)
    __shared__ float2 sB1[DEPTH][NQ];      // B-diag b1 (b0 == 1 gauge), d>=1
    __shared__ float2 sA0[DEPTH][NQ];      // A-diag a0 (temp, for G0)
    __shared__ float2 sG [DEPTH][NQ];      // g = a1*conj(a0)
    __shared__ float2 sG0[DEPTH];          // prod_i a0[d][i], d=1..4
    __shared__ float  sCd[DEPTH];          // prod_i scale[d][i], d=1..5
    __shared__ int    sM [DEPTH];          // per-layer X-flip mask (wire i -> bit 11-i)
    __shared__ float2 sPhi[DEPTH - 1][NT];      // per-layer per-thread fixed-bit phase
    __shared__ float2 sThi[DEPTH - 1][2][16];   // per-layer r-phase (x bit7 coupling)
    __shared__ float2 sW1[2][16];               // layer-1 fused product/diag table
    __shared__ float  sRed[NT / 32][NQ];

    const int t = threadIdx.x;
    const int b = blockIdx.x;

    if (t < DEPTH) sM[t] = 0;
    __syncthreads();

    // ================= Stage A: build gates; decompose U = (A*RY*B)*X =======
    if (t < DEPTH * NQ) {
        const int d = t / NQ, i = t % NQ;
        const float* pp = params + (d * NQ + i) * 3;
        float sa, ca, sb, cb, sg, cg;
        sincosf(0.5f * pp[0], &sa, &ca);
        sincosf(0.5f * pp[1], &sb, &cb);
        sincosf(0.5f * pp[2], &sg, &cg);
        float2 m00 = {  cb * ca, -sb * ca };
        float2 m01 = { -cb * sa,  sb * sa };
        float2 m10 = {  cb * sa,  sb * sa };
        float2 m11 = {  cb * ca,  sb * ca };
        float2 u00 = { cg * m00.x + sg * m10.y, cg * m00.y - sg * m10.x };
        float2 u01 = { cg * m01.x + sg * m11.y, cg * m01.y - sg * m11.x };
        float2 u10 = { sg * m00.y + cg * m10.x, -sg * m00.x + cg * m10.y };
        float2 u11 = { sg * m01.y + cg * m11.x, -sg * m01.x + cg * m11.y };
        if (d == 0) {
            float sx, cx;
            sincosf(0.5f * x[b * NQ + i], &sx, &cx);
            float2 v00 = { cx * u00.x + sx * u01.y,  cx * u00.y - sx * u01.x };
            float2 v01 = { sx * u00.y + cx * u01.x, -sx * u00.x + cx * u01.y };
            float2 v10 = { cx * u10.x + sx * u11.y,  cx * u10.y - sx * u11.x };
            float2 v11 = { sx * u10.y + cx * u11.x, -sx * u10.x + cx * u11.y };
            sU0[i][0] = v00; sU0[i][1] = v01; sU0[i][2] = v10; sU0[i][3] = v11;
        } else {
            float n00 = fmaf(u00.x, u00.x, u00.y * u00.y);   // |u00|^2
            float n10 = fmaf(u10.x, u10.x, u10.y * u10.y);   // |u10|^2
            bool swp = n10 > n00;     // V = U*X (column swap) so c' >= s'
            float2 v00, v10, v11;
            if (swp) { v00 = u01; v10 = u11; v11 = u10; atomicOr(&sM[d], 1 << (11 - i)); }
            else     { v00 = u00; v10 = u10; v11 = u11; }
            float c = sqrtf(fmaf(v00.x, v00.x, v00.y * v00.y));
            float s = sqrtf(fmaf(v10.x, v10.x, v10.y * v10.y));
            float ic = 1.0f / c;
            float2 a0 = { v00.x * ic, v00.y * ic };
            float2 a1, b1;
            if (s < 1e-12f) {
                a1 = { v11.x * ic, v11.y * ic };
                b1 = { 1.f, 0.f };
            } else {
                float is = 1.0f / s;
                a1 = { v10.x * is, v10.y * is };
                float2 tb = cmulc(v11, a1);
                b1 = { tb.x * ic, tb.y * ic };
            }
            sT [d][i] = s * ic;       // t = s/c <= 1
            sSc[d][i] = c;
            sB1[d][i] = b1;
            sA0[d][i] = a0;
            sG [d][i] = cmulc(a1, a0);
        }
    }
    __syncthreads();

    // ================= Stage B: per-layer products =========================
    if (t >= 1 && t <= 5) {
        float cs = 1.f;
        #pragma unroll
        for (int i = 0; i < NQ; ++i) cs *= sSc[t][i];
        sCd[t] = cs;
        if (t <= 4) {
            float2 p = { 1.f, 0.f };
            #pragma unroll
            for (int i = 0; i < NQ; ++i) p = cmul(p, sA0[t][i]);
            sG0[t] = p;
        }
    }
    __syncthreads();

    // ================= Stage C: diagonal tables ============================
    // Layer d: src = gray(dst ^ m_d) = gray(dst) ^ gm_d, gm = m ^ (m>>1).
    // B_d is dst-indexed (post-X); propagated A_{d-1} is src-indexed.
    #pragma unroll
    for (int k = 0; k < DEPTH - 1; ++k) {
        const int d = k + 1;
        const int mm = sM[d];
        const int gm = mm ^ (mm >> 1);
        float2 phi = (d >= 2) ? sG0[d - 1] : make_float2(1.f, 0.f);
        const float cd = sCd[d];
        phi.x *= cd; phi.y *= cd;
        #pragma unroll
        for (int i = 4; i < NQ; ++i)
            if ((t >> (11 - i)) & 1) phi = cmul(phi, sB1[d][i]);
        if (d >= 2) {
            #pragma unroll
            for (int i = 5; i < NQ; ++i)
                if (((t >> (11 - i)) ^ (t >> (12 - i)) ^ (gm >> (11 - i))) & 1)
                    phi = cmul(phi, sG[d - 1][i]);
        }
        sPhi[k][t] = phi;
    }
    if (t < (DEPTH - 1) * 32) {
        const int k = t / 32, e = (t >> 4) & 1, r = t & 15;
        const int d = k + 1;
        const int mm = sM[d];
        const int gm = mm ^ (mm >> 1);
        float2 T = { 1.f, 0.f };
        #pragma unroll
        for (int i = 0; i < 4; ++i)
            if ((r >> (3 - i)) & 1) T = cmul(T, sB1[d][i]);
        if (d >= 2) {
            int r0 = r & 1, r1 = (r >> 1) & 1, r2 = (r >> 2) & 1, r3 = (r >> 3) & 1;
            if ((r3      ^ (gm >> 11)) & 1) T = cmul(T, sG[d - 1][0]);
            if ((r2 ^ r3 ^ (gm >> 10)) & 1) T = cmul(T, sG[d - 1][1]);
            if ((r1 ^ r2 ^ (gm >>  9)) & 1) T = cmul(T, sG[d - 1][2]);
            if ((r0 ^ r1 ^ (gm >>  8)) & 1) T = cmul(T, sG[d - 1][3]);
            if ((e  ^ r0 ^ (gm >>  7)) & 1) T = cmul(T, sG[d - 1][4]);
        }
        sThi[k][e][r] = T;
    }
    __syncthreads();

    // ================= Stage D: layer-1 fused table + per-thread phiF ======
    // Layer-1 reads product state at src = gray(dst) ^ gm1.
    const int m1g = sM[1] ^ (sM[1] >> 1);
    if (t < 32) {
        const int e = t >> 4, r = t & 15;
        const int gr = (r ^ (r >> 1)) ^ ((m1g >> 8) & 15);
        float2 c01 = cmul(sU0[0][(gr & 8) ? 2 : 0], sU0[1][(gr & 4) ? 2 : 0]);
        float2 c23 = cmul(sU0[2][(gr & 2) ? 2 : 0], sU0[3][(gr & 1) ? 2 : 0]);
        float2 u4  = sU0[4][((e ^ r ^ (m1g >> 7)) & 1) ? 2 : 0];
        sW1[e][r] = cmul(cmul(c01, c23), cmul(u4, sThi[0][0][r]));
    }
    const int gt = t ^ (t >> 1);
    float2 phiF = sPhi[0][t];
    {
        const int gmix = gt ^ m1g;
        #pragma unroll
        for (int i = 5; i < NQ; ++i) {
            int bit = (gmix >> (11 - i)) & 1;
            phiF = cmul(phiF, sU0[i][bit ? 2 : 0]);
        }
    }
    __syncthreads();

    // ===== addressing bases (hot-loop addresses are base ^ const) ==========
    const int swt   = sw(t);                       // C store:  (r<<8) | swt
    const int swgt  = sw(gt);                      // C gather: (swgt^sw(gm)) ^ CR(r)
    const int baseB = ((t >> 4) << 8) | (t & 15);  // B:        baseB ^ 17r
    const int swA   = (t << 4) | (t & 15);         // A:        swA ^ r

    float2 s[PT];

    // ================= Layers 1..5 =========================================
    for (int d = 1; d < DEPTH; ++d) {
        // ---- Round C: wires 0..3 ----
        if (d == 1) {
            const float2* w1 = sW1[t >> 7];
            #pragma unroll
            for (int r = 0; r < PT; ++r) s[r] = cmul(w1[r], phiF);
        } else {
            const int k = d - 1;
            const int mm = sM[d];
            const int gm = mm ^ (mm >> 1);
            const int gbase = swgt ^ sw(gm);       // sw, gray are GF(2)-linear
            const float2 phi = sPhi[k][t];
            const float2* thi = sThi[k][(t >> 7) & 1];
            #pragma unroll
            for (int r = 0; r < PT; ++r) {
                const int gr = r ^ (r >> 1);
                const int cr = (gr << 8) ^ ((r & 1) << 7) ^ ((r & 1) << 3);
                s[r] = cmul(sS[gbase ^ cr], cmul(phi, thi[r]));
            }
            __syncthreads();           // all reads of old state done
        }
        #pragma unroll
        for (int j = 0; j < 4; ++j) {  // wire j -> local bit 3-j
            const int p = 3 - j;
            const float tv = sT[d][j];
            #pragma unroll
            for (int m = 0; m < 8; ++m) {
                int lo = m & ((1 << p) - 1);
                int i0 = ((m >> p) << (p + 1)) | lo;
                sh_pair(s[i0], s[i0 | (1 << p)], tv);
            }
        }
        #pragma unroll
        for (int r = 0; r < PT; ++r) sS[(r << 8) | swt] = s[r];
        __syncthreads();

        // ---- Round B: wires 4..7 (per-thread disjoint addresses) ----
        #pragma unroll
        for (int r = 0; r < PT; ++r) s[r] = sS[baseB ^ (17 * r)];
        #pragma unroll
        for (int j = 0; j < 4; ++j) {
            const int p = 3 - j;
            const float tv = sT[d][4 + j];
            #pragma unroll
            for (int m = 0; m < 8; ++m) {
                int lo = m & ((1 << p) - 1);
                int i0 = ((m >> p) << (p + 1)) | lo;
                sh_pair(s[i0], s[i0 | (1 << p)], tv);
            }
        }
        #pragma unroll
        for (int r = 0; r < PT; ++r) sS[baseB ^ (17 * r)] = s[r];
        __syncthreads();

        // ---- Round A: wires 8..11 ----
        #pragma unroll
        for (int r = 0; r < PT; ++r) s[r] = sS[swA ^ r];
        #pragma unroll
        for (int j = 0; j < 4; ++j) {
            const int p = 3 - j;
            const float tv = sT[d][8 + j];
            #pragma unroll
            for (int m = 0; m < 8; ++m) {
                int lo = m & ((1 << p) - 1);
                int i0 = ((m >> p) << (p + 1)) | lo;
                sh_pair(s[i0], s[i0 | (1 << p)], tv);
            }
        }
        if (d < DEPTH - 1) {
            #pragma unroll
            for (int r = 0; r < PT; ++r) sS[swA ^ r] = s[r];
            __syncthreads();
        }
    }

    // ==== Final reduction directly from registers (idx = (t<<4)|r). ====
    float accLo[4] = { 0.f, 0.f, 0.f, 0.f };
    float sumAll = 0.f;
    #pragma unroll
    for (int r = 0; r < PT; ++r) {
        float pr = fmaf(s[r].x, s[r].x, s[r].y * s[r].y);
        sumAll += pr;
        const int r3 = (r >> 3) & 1, r2 = (r >> 2) & 1, r1 = (r >> 1) & 1, r0 = r & 1;
        const int p8 = r3, p9 = r3 ^ r2, p10 = p9 ^ r1, p11 = p10 ^ r0;
        accLo[0] += p8  ? -pr : pr;
        accLo[1] += p9  ? -pr : pr;
        accLo[2] += p10 ? -pr : pr;
        accLo[3] += p11 ? -pr : pr;
    }

    float acc[NQ];
    int pref = 0;
    #pragma unroll
    for (int q = 0; q < 8; ++q) {
        pref ^= (t >> (7 - q)) & 1;
        acc[q] = pref ? -sumAll : sumAll;
    }
    const int ptp = pref;
    #pragma unroll
    for (int q = 0; q < 4; ++q) acc[8 + q] = ptp ? -accLo[q] : accLo[q];

    #pragma unroll
    for (int q = 0; q < NQ; ++q) {
        #pragma unroll
        for (int off = 16; off; off >>= 1)
            acc[q] += __shfl_xor_sync(0xffffffffu, acc[q], off);
    }
    if ((t & 31) == 0) {
        #pragma unroll
        for (int q = 0; q < NQ; ++q) sRed[t >> 5][q] = acc[q];
    }
    __syncthreads();
    if (t < NQ) {
        float sres = 0.f;
        #pragma unroll
        for (int w = 0; w < NT / 32; ++w) sres += sRed[w][t];
        out[b * NQ + t] = sres;
    }
}

} // namespace

extern "C" void kernel_launch(void* const* d_in, const int* in_sizes, int n_in,
                              void* d_out, int out_size)
{
    (void)n_in; (void)out_size;
    const float* x;
    const float* params;
    if (in_sizes[0] == DEPTH * NQ * 3) {
        params = (const float*)d_in[0];
        x      = (const float*)d_in[1];
    } else {
        x      = (const float*)d_in[0];
        params = (const float*)d_in[1];
    }
    qsim_kernel<<<4096, NT>>>(x, params, (float*)d_out);
}

// round 11
// speedup vs baseline: 1.6489x; 1.1155x over previous
#include <cuda_runtime.h>

namespace {

constexpr int NQ     = 12;
constexpr int DEPTH  = 6;
constexpr int NSTATE = 1 << NQ;        // 4096
constexpr int NT     = 256;            // threads per CTA
constexpr int PT     = NSTATE / NT;    // 16 amplitudes per thread
constexpr int NPAD   = NSTATE + (NSTATE >> 4);   // 4352: pad-17 rows

// Padded linear layout: phys(idx) = idx + (idx>>4) = 17*(idx>>4) + (idx&15).
// Injective into [0, 4351]; bank-conflict-free for all round patterns.

__device__ __forceinline__ float2 cmul(float2 a, float2 b) {
    float2 r;
    r.x = fmaf(a.x, b.x, -(a.y * b.y));
    r.y = fmaf(a.x, b.y, a.y * b.x);
    return r;
}
__device__ __forceinline__ float2 cmulc(float2 a, float2 b) {  // a * conj(b)
    float2 r;
    r.x = fmaf(a.x, b.x,  a.y * b.y);
    r.y = fmaf(a.y, b.x, -(a.x * b.y));
    return r;
}
// shear pair (fast Givens): na = a - t*b ; nb = t*a + b   (4 FMA total)
__device__ __forceinline__ void sh_pair(float2& a, float2& b, float tv) {
    float2 na, nb;
    na.x = fmaf(-tv, b.x, a.x);
    na.y = fmaf(-tv, b.y, a.y);
    nb.x = fmaf( tv, a.x, b.x);
    nb.y = fmaf( tv, a.y, b.y);
    a = na; b = nb;
}

__global__ void __launch_bounds__(NT, 4) qsim_kernel(const float* __restrict__ x,
                                                     const float* __restrict__ params,
                                                     float* __restrict__ out)
{
    __shared__ float2 sS[NPAD];            // state, padded layout (34.0 KB)
    __shared__ float2 sU0[NQ][4];          // layer-0 full matrices (batch-dependent)
    __shared__ float  sT [DEPTH][NQ];      // shear coeff t = s'/c' (<=1), d>=1
    __shared__ float  sSc[DEPTH][NQ];      // per-gate scale c'
    __shared__ float2 sB1[DEPTH][NQ];      // B-diag b1 (b0 == 1 gauge), d>=1
    __shared__ float2 sA0[DEPTH][NQ];      // A-diag a0 (temp, for G0)
    __shared__ float2 sG [DEPTH][NQ];      // g = a1*conj(a0)
    __shared__ float2 sG0[DEPTH];          // prod_i a0[d][i], d=1..4
    __shared__ float  sCd[DEPTH];          // prod_i scale[d][i], d=1..5
    __shared__ int    sM [DEPTH];          // per-layer X-flip mask (wire i -> bit 11-i)
    __shared__ float2 sPhiA[DEPTH - 1][16];     // phase over t bits [7:4]
    __shared__ float2 sPhiB[DEPTH - 1][2][16];  // phase over t bits [3:0] (x bit4)
    __shared__ float2 sThi [DEPTH - 1][2][16];  // phase over r bits (x bit7 coupling)
    __shared__ float2 sW1[2][16];               // layer-1 fused product/diag table
    __shared__ float  sRed[NT / 32][NQ];

    const int t = threadIdx.x;
    const int b = blockIdx.x;

    if (t < DEPTH) sM[t] = 0;
    __syncthreads();

    // ================= Stage A: build gates; decompose U = (A*RY*B)*X =======
    if (t < DEPTH * NQ) {
        const int d = t / NQ, i = t % NQ;
        const float* pp = params + (d * NQ + i) * 3;
        float sa, ca, sb, cb, sg, cg;
        sincosf(0.5f * pp[0], &sa, &ca);
        sincosf(0.5f * pp[1], &sb, &cb);
        sincosf(0.5f * pp[2], &sg, &cg);
        float2 m00 = {  cb * ca, -sb * ca };
        float2 m01 = { -cb * sa,  sb * sa };
        float2 m10 = {  cb * sa,  sb * sa };
        float2 m11 = {  cb * ca,  sb * ca };
        float2 u00 = { cg * m00.x + sg * m10.y, cg * m00.y - sg * m10.x };
        float2 u01 = { cg * m01.x + sg * m11.y, cg * m01.y - sg * m11.x };
        float2 u10 = { sg * m00.y + cg * m10.x, -sg * m00.x + cg * m10.y };
        float2 u11 = { sg * m01.y + cg * m11.x, -sg * m01.x + cg * m11.y };
        if (d == 0) {
            float sx, cx;
            sincosf(0.5f * x[b * NQ + i], &sx, &cx);
            float2 v00 = { cx * u00.x + sx * u01.y,  cx * u00.y - sx * u01.x };
            float2 v01 = { sx * u00.y + cx * u01.x, -sx * u00.x + cx * u01.y };
            float2 v10 = { cx * u10.x + sx * u11.y,  cx * u10.y - sx * u11.x };
            float2 v11 = { sx * u10.y + cx * u11.x, -sx * u10.x + cx * u11.y };
            sU0[i][0] = v00; sU0[i][1] = v01; sU0[i][2] = v10; sU0[i][3] = v11;
        } else {
            float n00 = fmaf(u00.x, u00.x, u00.y * u00.y);
            float n10 = fmaf(u10.x, u10.x, u10.y * u10.y);
            bool swp = n10 > n00;     // V = U*X (column swap) so c' >= s'
            float2 v00, v10, v11;
            if (swp) { v00 = u01; v10 = u11; v11 = u10; atomicOr(&sM[d], 1 << (11 - i)); }
            else     { v00 = u00; v10 = u10; v11 = u11; }
            float c = sqrtf(fmaf(v00.x, v00.x, v00.y * v00.y));
            float s = sqrtf(fmaf(v10.x, v10.x, v10.y * v10.y));
            float ic = 1.0f / c;
            float2 a0 = { v00.x * ic, v00.y * ic };
            float2 a1, b1;
            if (s < 1e-12f) {
                a1 = { v11.x * ic, v11.y * ic };
                b1 = { 1.f, 0.f };
            } else {
                float is = 1.0f / s;
                a1 = { v10.x * is, v10.y * is };
                float2 tb = cmulc(v11, a1);
                b1 = { tb.x * ic, tb.y * ic };
            }
            sT [d][i] = s * ic;
            sSc[d][i] = c;
            sB1[d][i] = b1;
            sA0[d][i] = a0;
            sG [d][i] = cmulc(a1, a0);
        }
    }
    __syncthreads();

    // ================= Stage B: per-layer products =========================
    if (t >= 1 && t <= 5) {
        float cs = 1.f;
        #pragma unroll
        for (int i = 0; i < NQ; ++i) cs *= sSc[t][i];
        sCd[t] = cs;
        if (t <= 4) {
            float2 p = { 1.f, 0.f };
            #pragma unroll
            for (int i = 0; i < NQ; ++i) p = cmul(p, sA0[t][i]);
            sG0[t] = p;
        }
    }
    __syncthreads();

    // ================= Stage C: factorized diagonal tables =================
    // dst = (r<<8)|t ; src = gray(dst) ^ gm_d.
    // D_d(dst) = PhiA[t>>4] * PhiB[bit4(t)][t&15] * Thi[bit7(t)][r].
    if (t < (DEPTH - 1) * 16) {            // PhiA: t bits 7..4 (wires 4..7)
        const int k = t >> 4, h = t & 15;  // h = consumer's t bits [7:4]
        const int d = k + 1;
        const int mm = sM[d];
        const int gm = mm ^ (mm >> 1);
        float2 P = (d >= 2) ? sG0[d - 1] : make_float2(1.f, 0.f);
        const float cd = sCd[d];
        P.x *= cd; P.y *= cd;
        #pragma unroll
        for (int i = 4; i <= 7; ++i)       // wire i -> t bit (11-i) = h bit (7-i)
            if ((h >> (7 - i)) & 1) P = cmul(P, sB1[d][i]);
        if (d >= 2) {                      // couplings i=5,6,7: t bits (6,7),(5,6),(4,5)
            if (((h >> 2) ^ (h >> 3) ^ (gm >> 6)) & 1) P = cmul(P, sG[d - 1][5]);
            if (((h >> 1) ^ (h >> 2) ^ (gm >> 5)) & 1) P = cmul(P, sG[d - 1][6]);
            if (((h >> 0) ^ (h >> 1) ^ (gm >> 4)) & 1) P = cmul(P, sG[d - 1][7]);
        }
        sPhiA[k][h] = P;
    } else if (t < (DEPTH - 1) * 16 + (DEPTH - 1) * 32) {  // PhiB: t bits 3..0 (x bit4)
        const int tt = t - (DEPTH - 1) * 16;
        const int k = tt >> 5, e4 = (tt >> 4) & 1, l = tt & 15;
        const int d = k + 1;
        const int mm = sM[d];
        const int gm = mm ^ (mm >> 1);
        float2 P = { 1.f, 0.f };
        #pragma unroll
        for (int i = 8; i <= 11; ++i)      // wire i -> t bit (11-i) = l bit (11-i)
            if ((l >> (11 - i)) & 1) P = cmul(P, sB1[d][i]);
        if (d >= 2) {
            if (((l >> 3) ^ e4       ^ (gm >> 3)) & 1) P = cmul(P, sG[d - 1][8]);   // bits 3^4
            if (((l >> 2) ^ (l >> 3) ^ (gm >> 2)) & 1) P = cmul(P, sG[d - 1][9]);   // bits 2^3
            if (((l >> 1) ^ (l >> 2) ^ (gm >> 1)) & 1) P = cmul(P, sG[d - 1][10]);  // bits 1^2
            if (((l >> 0) ^ (l >> 1) ^ (gm >> 0)) & 1) P = cmul(P, sG[d - 1][11]);  // bits 0^1
        }
        sPhiB[k][e4][l] = P;
    }
    if (t < (DEPTH - 1) * 32) {            // Thi: wires 0..3 (+ couplings 0..4)
        const int k = t / 32, e = (t >> 4) & 1, r = t & 15;
        const int d = k + 1;
        const int mm = sM[d];
        const int gm = mm ^ (mm >> 1);
        float2 T = { 1.f, 0.f };
        #pragma unroll
        for (int i = 0; i < 4; ++i)
            if ((r >> (3 - i)) & 1) T = cmul(T, sB1[d][i]);
        if (d >= 2) {
            int r0 = r & 1, r1 = (r >> 1) & 1, r2 = (r >> 2) & 1, r3 = (r >> 3) & 1;
            if ((r3      ^ (gm >> 11)) & 1) T = cmul(T, sG[d - 1][0]);
            if ((r2 ^ r3 ^ (gm >> 10)) & 1) T = cmul(T, sG[d - 1][1]);
            if ((r1 ^ r2 ^ (gm >>  9)) & 1) T = cmul(T, sG[d - 1][2]);
            if ((r0 ^ r1 ^ (gm >>  8)) & 1) T = cmul(T, sG[d - 1][3]);
            if ((e  ^ r0 ^ (gm >>  7)) & 1) T = cmul(T, sG[d - 1][4]);
        }
        sThi[k][e][r] = T;
    }
    __syncthreads();

    // ================= Stage D: layer-1 fused table + per-thread phiF ======
    const int m1g = sM[1] ^ (sM[1] >> 1);
    if (t < 32) {
        const int e = t >> 4, r = t & 15;
        const int gr = (r ^ (r >> 1)) ^ ((m1g >> 8) & 15);
        float2 c01 = cmul(sU0[0][(gr & 8) ? 2 : 0], sU0[1][(gr & 4) ? 2 : 0]);
        float2 c23 = cmul(sU0[2][(gr & 2) ? 2 : 0], sU0[3][(gr & 1) ? 2 : 0]);
        float2 u4  = sU0[4][((e ^ r ^ (m1g >> 7)) & 1) ? 2 : 0];
        sW1[e][r] = cmul(cmul(c01, c23), cmul(u4, sThi[0][0][r]));
    }
    const int gt = t ^ (t >> 1);
    float2 phiF;
    {
        float2 p = cmul(sPhiA[0][t >> 4], sPhiB[0][(t >> 4) & 1][t & 15]);
        const int gmix = gt ^ m1g;
        #pragma unroll
        for (int i = 5; i < NQ; ++i) {
            int bit = (gmix >> (11 - i)) & 1;
            p = cmul(p, sU0[i][bit ? 2 : 0]);
        }
        phiF = p;
    }
    __syncthreads();

    // ===== addressing bases (pad-17: phys = idx + (idx>>4)) ================
    const int swt_p   = t + (t >> 4);                              // C store: + 272r
    const int baseB_p = (((t >> 4) << 8) | (t & 15)) + ((t >> 4) << 4);  // B: + 17v
    const int baseA_p = 17 * t;                                    // A: + r

    float2 s[PT];

    // ================= Layers 1..5 =========================================
    for (int d = 1; d < DEPTH; ++d) {
        // ---- Round C: wires 0..3 ----
        if (d == 1) {
            const float2* w1 = sW1[t >> 7];
            #pragma unroll
            for (int r = 0; r < PT; ++r) s[r] = cmul(w1[r], phiF);
        } else {
            const int k = d - 1;
            const int mm = sM[d];
            const int gIdx = gt ^ (mm ^ (mm >> 1));
            const float2 phi = cmul(sPhiA[k][t >> 4], sPhiB[k][(t >> 4) & 1][t & 15]);
            const float2* thi = sThi[k][(t >> 7) & 1];
            #pragma unroll
            for (int r = 0; r < PT; ++r) {
                const int gr = r ^ (r >> 1);
                // logical src index ONLY (no swizzle artifact):
                const int cr = (gr << 8) ^ ((r & 1) << 7);
                const int idxl = gIdx ^ cr;
                s[r] = cmul(sS[idxl + (idxl >> 4)], cmul(phi, thi[r]));
            }
            __syncthreads();           // all reads of old state done
        }
        #pragma unroll
        for (int j = 0; j < 4; ++j) {  // wire j -> local bit 3-j
            const int p = 3 - j;
            const float tv = sT[d][j];
            #pragma unroll
            for (int m = 0; m < 8; ++m) {
                int lo = m & ((1 << p) - 1);
                int i0 = ((m >> p) << (p + 1)) | lo;
                sh_pair(s[i0], s[i0 | (1 << p)], tv);
            }
        }
        #pragma unroll
        for (int r = 0; r < PT; ++r) sS[swt_p + 272 * r] = s[r];
        __syncthreads();

        // ---- Round B: wires 4..7 (per-thread disjoint addresses) ----
        #pragma unroll
        for (int r = 0; r < PT; ++r) s[r] = sS[baseB_p + 17 * r];
        #pragma unroll
        for (int j = 0; j < 4; ++j) {
            const int p = 3 - j;
            const float tv = sT[d][4 + j];
            #pragma unroll
            for (int m = 0; m < 8; ++m) {
                int lo = m & ((1 << p) - 1);
                int i0 = ((m >> p) << (p + 1)) | lo;
                sh_pair(s[i0], s[i0 | (1 << p)], tv);
            }
        }
        #pragma unroll
        for (int r = 0; r < PT; ++r) sS[baseB_p + 17 * r] = s[r];
        __syncthreads();

        // ---- Round A: wires 8..11 ----
        #pragma unroll
        for (int r = 0; r < PT; ++r) s[r] = sS[baseA_p + r];
        #pragma unroll
        for (int j = 0; j < 4; ++j) {
            const int p = 3 - j;
            const float tv = sT[d][8 + j];
            #pragma unroll
            for (int m = 0; m < 8; ++m) {
                int lo = m & ((1 << p) - 1);
                int i0 = ((m >> p) << (p + 1)) | lo;
                sh_pair(s[i0], s[i0 | (1 << p)], tv);
            }
        }
        if (d < DEPTH - 1) {
            #pragma unroll
            for (int r = 0; r < PT; ++r) sS[baseA_p + r] = s[r];
            __syncthreads();
        }
    }

    // ==== Final reduction directly from registers (idx = (t<<4)|r). ====
    float accLo[4] = { 0.f, 0.f, 0.f, 0.f };
    float sumAll = 0.f;
    #pragma unroll
    for (int r = 0; r < PT; ++r) {
        float pr = fmaf(s[r].x, s[r].x, s[r].y * s[r].y);
        sumAll += pr;
        const int r3 = (r >> 3) & 1, r2 = (r >> 2) & 1, r1 = (r >> 1) & 1, r0 = r & 1;
        const int p8 = r3, p9 = r3 ^ r2, p10 = p9 ^ r1, p11 = p10 ^ r0;
        accLo[0] += p8  ? -pr : pr;
        accLo[1] += p9  ? -pr : pr;
        accLo[2] += p10 ? -pr : pr;
        accLo[3] += p11 ? -pr : pr;
    }

    float acc[NQ];
    int pref = 0;
    #pragma unroll
    for (int q = 0; q < 8; ++q) {
        pref ^= (t >> (7 - q)) & 1;
        acc[q] = pref ? -sumAll : sumAll;
    }
    const int ptp = pref;
    #pragma unroll
    for (int q = 0; q < 4; ++q) acc[8 + q] = ptp ? -accLo[q] : accLo[q];

    #pragma unroll
    for (int q = 0; q < NQ; ++q) {
        #pragma unroll
        for (int off = 16; off; off >>= 1)
            acc[q] += __shfl_xor_sync(0xffffffffu, acc[q], off);
    }
    if ((t & 31) == 0) {
        #pragma unroll
        for (int q = 0; q < NQ; ++q) sRed[t >> 5][q] = acc[q];
    }
    __syncthreads();
    if (t < NQ) {
        float sres = 0.f;
        #pragma unroll
        for (int w = 0; w < NT / 32; ++w) sres += sRed[w][t];
        out[b * NQ + t] = sres;
    }
}

} // namespace

extern "C" void kernel_launch(void* const* d_in, const int* in_sizes, int n_in,
                              void* d_out, int out_size)
{
    (void)n_in; (void)out_size;
    const float* x;
    const float* params;
    if (in_sizes[0] == DEPTH * NQ * 3) {
        params = (const float*)d_in[0];
        x      = (const float*)d_in[1];
    } else {
        x      = (const float*)d_in[0];
        params = (const float*)d_in[1];
    }
    qsim_kernel<<<4096, NT>>>(x, params, (float*)d_out);
}